// round 12
// baseline (speedup 1.0000x reference)
#include <cuda_runtime.h>
#include <math.h>

#define N_TOT    87296
#define SEL_TOT  4256
#define SEL_PAD  4352
#define SEL_PAD2 4352
#define WW       136
#define JTILES   34
#define EQCAP    4096
#define HBINS    8192
#define MPITCH   137
#define RTILE    128

// ---------------- scratch (device globals; no allocations) -----------------
__device__ float    g_key[N_TOT];
__device__ int      g_cls[N_TOT];
__device__ float    g_selKey[SEL_TOT];
__device__ int      g_selCls[SEL_TOT];
__device__ int      g_selTie[SEL_TOT];
__device__ float4   g_selBox[SEL_TOT];
__device__ float    g_srtScore[SEL_PAD];
__device__ int      g_srtCls[SEL_PAD];
__device__ int      g_srtValid[SEL_PAD];
__device__ float4   g_srtBox[SEL_PAD];
__device__ unsigned long long g_bufA[N_TOT];
__device__ unsigned g_hist[5 * HBINS];          // reset at end of nmsKernel
__device__ unsigned g_b13[5];
__device__ int      g_need[5];
__device__ int      g_cg[5];                    // reset at end of nmsKernel
__device__ int      g_cntTie[5];                // reset at end of nmsKernel
__device__ unsigned g_Mt[(size_t)WW * SEL_PAD2]; // column-major: Mt[w][j]
__device__ unsigned g_keep[2][WW];
__device__ unsigned g_keepOut[WW];
__device__ unsigned g_changeArr[16];
__device__ unsigned g_barCount = 0;
__device__ unsigned g_barGen   = 0;             // monotonic across replays

__device__ __forceinline__ unsigned fflip(float f) {
    unsigned u = __float_as_uint(f);
    return (u & 0x80000000u) ? ~u : (u | 0x80000000u);
}

__constant__ int c_OFF[5]  = {0, 65536, 81920, 86016, 87040};
__constant__ int c_SOFF[5] = {0, 1000, 2000, 3000, 4000};
__constant__ int c_K[5]    = {1000, 1000, 1000, 1000, 256};

// ------- 1. per-anchor class max + fused histogram (warp per anchor) -------
__global__ void scoreKernel(const float* __restrict__ c0, const float* __restrict__ c1,
                            const float* __restrict__ c2, const float* __restrict__ c3,
                            const float* __restrict__ c4) {
    int warp = (blockIdx.x * blockDim.x + threadIdx.x) >> 5;
    int lane = threadIdx.x & 31;
    if (warp >= N_TOT) return;
    int off, lvl;
    const float* base;
    if      (warp < 65536) { off = 0;     base = c0; lvl = 0; }
    else if (warp < 81920) { off = 65536; base = c1; lvl = 1; }
    else if (warp < 86016) { off = 81920; base = c2; lvl = 2; }
    else if (warp < 87040) { off = 86016; base = c3; lvl = 3; }
    else                   { off = 87040; base = c4; lvl = 4; }
    int a = warp - off;
    float v = -1e30f; int bi = 1 << 20;
    if (lane < 20) {
        const float4* p4 = reinterpret_cast<const float4*>(base + (size_t)a * 80);
        float4 q = p4[lane];
        int cb = lane * 4;
        v = q.x; bi = cb;
        if (q.y > v) { v = q.y; bi = cb + 1; }
        if (q.z > v) { v = q.z; bi = cb + 2; }
        if (q.w > v) { v = q.w; bi = cb + 3; }
    }
    for (int o = 16; o; o >>= 1) {
        float ov = __shfl_down_sync(0xffffffffu, v, o);
        int   oi = __shfl_down_sync(0xffffffffu, bi, o);
        if (ov > v || (ov == v && oi < bi)) { v = ov; bi = oi; }
    }
    if (lane == 0) {
        float ps = 1.0f / (1.0f + expf(-v));
        float kf = (ps > 0.05f) ? ps : -1.0f;
        g_key[warp] = kf;
        g_cls[warp] = bi + 1;
        atomicAdd(&g_hist[lvl * HBINS + (fflip(kf) >> 19)], 1u);  // RED, no return
    }
}

// ------- 2a. pivot per level (5 blocks, fully parallel scans) --------------
__global__ void pivotKernel() {
    int lvl = blockIdx.x, tid = threadIdx.x;
    __shared__ unsigned sfx[256], coarse[256];
    __shared__ int sCb, sAcc;
    const unsigned* H = g_hist + lvl * HBINS;
    unsigned s = 0;
    #pragma unroll 8
    for (int j = 0; j < 32; j++) s += H[tid * 32 + j];
    coarse[tid] = s;
    sfx[tid] = s;
    __syncthreads();
    for (int d = 1; d < 256; d <<= 1) {              // suffix scan (Hillis-Steele)
        unsigned v = (tid + d < 256) ? sfx[tid + d] : 0u;
        __syncthreads();
        sfx[tid] += v;
        __syncthreads();
    }
    unsigned k = (unsigned)c_K[lvl];
    unsigned incl = sfx[tid], excl = incl - coarse[tid];
    if (incl >= k && excl < k) { sCb = tid; sAcc = (int)excl; }
    __syncthreads();
    int cb = sCb;
    unsigned kk = k - (unsigned)sAcc;
    if (tid < 32) {
        unsigned hv = H[cb * 32 + tid];
        unsigned x = hv;
        #pragma unroll
        for (int d = 1; d < 32; d <<= 1) {
            unsigned y = __shfl_down_sync(0xffffffffu, x, d);
            if (tid + d < 32) x += y;
        }
        unsigned excl2 = x - hv;
        if (x >= kk && excl2 < kk) {
            g_b13[lvl]  = (unsigned)(cb * 32 + tid);
            g_need[lvl] = (int)(kk - excl2);
        }
    }
}

// ---------------- common: write one selected candidate ---------------------
__device__ __forceinline__ void writeSel(int slot, float kf, int gidx, int lvl, int i,
                                         const float* __restrict__ reg,
                                         float l0, float l1, float l2, float l3) {
    g_selKey[slot] = kf;
    g_selCls[slot] = g_cls[gidx];
    g_selTie[slot] = (lvl << 17) | i;
    float b0 = reg[(size_t)i * 4 + 0], b1 = reg[(size_t)i * 4 + 1];
    float b2 = reg[(size_t)i * 4 + 2], b3 = reg[(size_t)i * 4 + 3];
    g_selBox[slot] = make_float4(fmaxf(b0, l0), fmaxf(b1, l1),
                                 fminf(b2, l2), fminf(b3, l3));
}

// ------- 2b. fill winners + tie buffer (341 blocks) ------------------------
__global__ void fillKernel(const float* __restrict__ r0, const float* __restrict__ r1,
                           const float* __restrict__ r2, const float* __restrict__ r3,
                           const float* __restrict__ r4, const float* __restrict__ loc) {
    int b = blockIdx.x, lvl, start;
    if      (b < 256) { lvl = 0; start = b * 256; }
    else if (b < 320) { lvl = 1; start = 65536 + (b - 256) * 256; }
    else if (b < 336) { lvl = 2; start = 81920 + (b - 320) * 256; }
    else if (b < 340) { lvl = 3; start = 86016 + (b - 336) * 256; }
    else              { lvl = 4; start = 87040; }
    unsigned b13 = g_b13[lvl];
    int off = c_OFF[lvl], sbase = c_SOFF[lvl];
    const float* reg = (lvl == 0) ? r0 : (lvl == 1) ? r1 : (lvl == 2) ? r2 : (lvl == 3) ? r3 : r4;
    float l0 = loc[0], l1 = loc[1], l2 = loc[2], l3 = loc[3];
    int tid = threadIdx.x, lane = tid & 31;
    int idx = start + tid;
    float kf = g_key[idx];
    unsigned u = fflip(kf);
    unsigned top = u >> 19;
    bool win = top > b13;
    bool tie = top == b13;
    unsigned wb = __ballot_sync(0xffffffffu, win);
    if (wb) {
        int ld = __ffs(wb) - 1; int bs = 0;
        if (lane == ld) bs = atomicAdd(&g_cg[lvl], __popc(wb));
        bs = __shfl_sync(0xffffffffu, bs, ld);
        if (win) {
            int slot = sbase + bs + __popc(wb & ((1u << lane) - 1u));
            writeSel(slot, kf, idx, lvl, idx - off, reg, l0, l1, l2, l3);
        }
    }
    unsigned tb = __ballot_sync(0xffffffffu, tie);
    if (tb) {
        int ld = __ffs(tb) - 1; int bs = 0;
        if (lane == ld) bs = atomicAdd(&g_cntTie[lvl], __popc(tb));
        bs = __shfl_sync(0xffffffffu, bs, ld);
        if (tie) {
            int t = bs + __popc(tb & ((1u << lane) - 1u));
            g_bufA[off + t] = ((unsigned long long)u << 32) | (unsigned)(idx - off);
        }
    }
}

// ------- 2c. tie resolution by direct rank (5 x 32 blocks, 2 thr/elem) -----
__global__ void refineKernel(const float* __restrict__ r0, const float* __restrict__ r1,
                             const float* __restrict__ r2, const float* __restrict__ r3,
                             const float* __restrict__ r4, const float* __restrict__ loc) {
    int lvl = blockIdx.x;
    int tile = blockIdx.y;
    int tid = threadIdx.x;
    int need = g_need[lvl];
    int m = g_cntTie[lvl]; if (m > EQCAP) m = EQCAP;
    int lo = tile * RTILE;
    if (lo >= m || need <= 0) return;
    int off = c_OFF[lvl], sbase = c_SOFF[lvl];
    const float* reg = (lvl == 0) ? r0 : (lvl == 1) ? r1 : (lvl == 2) ? r2 : (lvl == 3) ? r3 : r4;
    float l0 = loc[0], l1 = loc[1], l2 = loc[2], l3 = loc[3];
    __shared__ unsigned long long ee[EQCAP];
    __shared__ int part[256];
    for (int i = tid; i < m; i += 256) {
        unsigned long long e = g_bufA[off + i];
        unsigned u = (unsigned)(e >> 32);
        unsigned idx = (unsigned)e;
        ee[i] = ((unsigned long long)u << 32) | (0xFFFFFFFFu - idx);  // value desc, idx asc
    }
    __syncthreads();
    int e_i = lo + (tid & 127);
    int seg = tid >> 7;                         // 0..1
    int mq = (m + 1) >> 1;
    int cnt = 0;
    if (e_i < m) {
        unsigned long long mine = ee[e_i];
        int a = seg * mq, bq = a + mq; if (bq > m) bq = m;
        for (int q = a; q < bq; q++) cnt += (ee[q] > mine) ? 1 : 0;
    }
    part[tid] = cnt;
    __syncthreads();
    if (seg == 0 && e_i < m) {
        int rank = part[tid] + part[tid + 128];
        if (rank < need) {                      // exact top_k tie rule; order irrelevant
            int idx = (int)(0xFFFFFFFFu - (unsigned)ee[e_i]);
            int slot = sbase + atomicAdd(&g_cg[lvl], 1);
            writeSel(slot, g_key[off + idx], off + idx, lvl, idx, reg, l0, l1, l2, l3);
        }
    }
}

// ---------------- 3. rank-sort, 8 threads per element (68 blocks) ----------
__global__ void rankKernel() {
    __shared__ unsigned long long sk[SEL_TOT];
    __shared__ int part[512];
    int tid = threadIdx.x;
    for (int i = tid; i < SEL_TOT; i += 512) {
        float kf = g_selKey[i];
        float ss = (kf > 0.0f) ? kf : 0.0f;
        unsigned tie = (unsigned)g_selTie[i];
        sk[i] = ((unsigned long long)fflip(ss) << 20) |
                (unsigned long long)(0xFFFFFu - tie);
    }
    __syncthreads();
    int e = blockIdx.x * 64 + (tid & 63);
    int seg = tid >> 6;                       // 0..7, 532 elements each
    int cnt = 0;
    if (e < SEL_TOT) {
        unsigned long long mine = sk[e];
        int lo = seg * 532, hi = lo + 532;    // 8*532 = 4256
        #pragma unroll 4
        for (int i = lo; i < hi; i++) cnt += (sk[i] > mine) ? 1 : 0;
    }
    part[tid] = cnt;
    __syncthreads();
    if (seg == 0 && e < SEL_TOT) {
        int rank = 0;
        #pragma unroll
        for (int s = 0; s < 8; s++) rank += part[(tid & 63) + s * 64];
        float kf = g_selKey[e];
        g_srtScore[rank] = (kf > 0.0f) ? kf : 0.0f;
        g_srtValid[rank] = (kf > 0.0f) ? 1 : 0;
        g_srtCls[rank]   = g_selCls[e];
        g_srtBox[rank]   = g_selBox[e];
    }
    if (blockIdx.x == 0 && tid < 16) g_changeArr[tid] = 0u;
}

// ------- 4. suppression bitmask, 2 j's per thread (grid 17x17) -------------
__global__ void matrixKernel() {
    int jbase = blockIdx.x * 256;
    int kbase = blockIdx.y * 256;
    if (kbase >= jbase + 256) return;            // slab entirely above diagonal
    __shared__ float4 kb[256];
    __shared__ float  ka[256];
    int tid = threadIdx.x;
    for (int t = tid; t < 256; t += 128) {
        int kk = kbase + t;
        float4 b = (kk < SEL_TOT) ? g_srtBox[kk] : make_float4(0.f, 0.f, 0.f, 0.f);
        kb[t] = b;
        ka[t] = fmaxf(b.z - b.x, 0.f) * fmaxf(b.w - b.y, 0.f);
    }
    __syncthreads();
    int j0 = jbase + tid;
    int j1 = j0 + 128;                           // both < SEL_PAD (4352)
    float4 b0 = g_srtBox[j0];
    float4 b1 = g_srtBox[j1];
    float a0 = fmaxf(b0.z - b0.x, 0.f) * fmaxf(b0.w - b0.y, 0.f);
    float a1 = fmaxf(b1.z - b1.x, 0.f) * fmaxf(b1.w - b1.y, 0.f);
    int wg = kbase >> 5;
    for (int wi = 0; wi < 8; wi++) {
        int kw0 = kbase + wi * 32;
        if (kw0 >= j1) break;                    // no j in this thread needs further words
        unsigned m0 = 0u, m1 = 0u;
        int tb = wi * 32;
        #pragma unroll
        for (int t = 0; t < 32; t++) {
            int k = kw0 + t;
            float4 bk = kb[tb + t];
            float ak = ka[tb + t];
            float iy1a = fmaxf(bk.x, b0.x), ix1a = fmaxf(bk.y, b0.y);
            float iy2a = fminf(bk.z, b0.z), ix2a = fminf(bk.w, b0.w);
            float inter0 = fmaxf(iy2a - iy1a, 0.f) * fmaxf(ix2a - ix1a, 0.f);
            bool bit0 = (k < j0) && (inter0 > 0.5f * fmaxf(a0 + ak - inter0, 1e-9f));
            if (bit0) m0 |= (1u << t);
            float iy1b = fmaxf(bk.x, b1.x), ix1b = fmaxf(bk.y, b1.y);
            float iy2b = fminf(bk.z, b1.z), ix2b = fminf(bk.w, b1.w);
            float inter1 = fmaxf(iy2b - iy1b, 0.f) * fmaxf(ix2b - ix1b, 0.f);
            bool bit1 = (k < j1) && (inter1 > 0.5f * fmaxf(a1 + ak - inter1, 1e-9f));
            if (bit1) m1 |= (1u << t);
        }
        if (kw0 < j0 && j0 < SEL_TOT) g_Mt[(size_t)(wg + wi) * SEL_PAD2 + j0] = m0;
        if (j1 < SEL_TOT)             g_Mt[(size_t)(wg + wi) * SEL_PAD2 + j1] = m1;
    }
}

// -- 5. 16 Jacobi iterations + final output fused (grid barrier, 34 blocks) --
__device__ __forceinline__ void gridBarrier(unsigned nb) {
    __threadfence();
    __syncthreads();
    if (threadIdx.x == 0) {
        unsigned my = atomicAdd(&g_barGen, 0u);
        if (atomicAdd(&g_barCount, 1u) == nb - 1u) {
            atomicExch(&g_barCount, 0u);
            __threadfence();
            atomicAdd(&g_barGen, 1u);
        } else {
            while (atomicAdd(&g_barGen, 0u) == my) __nanosleep(32);
        }
    }
    __syncthreads();
}

extern __shared__ unsigned sMdyn[];              // 128 * MPITCH words
__global__ void nmsKernel(float* __restrict__ out, const float* __restrict__ loc,
                          int out_size) {
    __shared__ unsigned sK[WW];
    int tid = threadIdx.x;
    int j = blockIdx.x * 128 + tid;
    int lane = tid & 31;
    int wj = j >> 5;
    int wtop = (j > 0 && j < SEL_TOT) ? (((j - 1) >> 5) + 1) : 0;
    unsigned* mrow = sMdyn + tid * MPITCH;
    for (int w = 0; w < WW; w++)                  // coalesced across tid
        mrow[w] = g_Mt[(size_t)w * SEL_PAD2 + j];
    unsigned lastBal = 0xFFFFFFFFu;

    for (int t = 0; t < 16; t++) {
        if (t == 0) {
            for (int w = tid; w < WW; w += 128) sK[w] = 0xFFFFFFFFu;
        } else {
            const unsigned* src = g_keep[(t - 1) & 1];
            for (int w = tid; w < WW; w += 128) sK[w] = __ldcg(&src[w]);
        }
        __syncthreads();
        unsigned acc = 0u;
        #pragma unroll 4
        for (int w = 0; w < wtop; w++) acc |= mrow[w] & sK[w];
        bool keepNew = (acc == 0u);
        unsigned bal = __ballot_sync(0xffffffffu, keepNew);
        unsigned oldw = sK[wj];
        if (lane == 0) {
            __stcg(&g_keep[t & 1][wj], bal);
            if (bal != oldw) atomicOr(&g_changeArr[t], 1u);
        }
        lastBal = bal;
        gridBarrier(JTILES);
        unsigned chg = __ldcg(&g_changeArr[t]);
        __syncthreads();
        if (chg == 0u) break;
    }
    if (lane == 0) __stcg(&g_keepOut[wj], lastBal);
    gridBarrier(JTILES);                         // keepOut globally visible

    // ---- fused final phase ----
    if (blockIdx.x != 0) {
        // parallel state reset for next execution (first exec uses zero-init)
        int nb = (int)gridDim.x - 1;             // blocks 1..33
        int total = 5 * HBINS;
        int per = (total + nb - 1) / nb;
        int lo = (blockIdx.x - 1) * per, hi = lo + per; if (hi > total) hi = total;
        for (int i = lo + tid; i < hi; i += 128) g_hist[i] = 0u;
        return;
    }
    if (tid < 5) { g_cg[tid] = 0; g_cntTie[tid] = 0; }

    __shared__ unsigned kw[WW];
    __shared__ int wpfx[WW + 1];
    __shared__ int sel[100];
    __shared__ int sKtot;
    for (int w = tid; w < WW; w += 128) {
        unsigned vb = 0u;
        int base = w * 32;
        #pragma unroll 4
        for (int b = 0; b < 32; b++) {
            int jj = base + b;
            if (jj < SEL_TOT && g_srtValid[jj]) vb |= (1u << b);
        }
        kw[w] = __ldcg(&g_keepOut[w]) & vb;
    }
    __syncthreads();
    if (tid == 0) {
        int acc = 0;
        for (int w = 0; w < WW; w++) { wpfx[w] = acc; acc += __popc(kw[w]); }
        wpfx[WW] = acc;
        sKtot = acc;
    }
    __syncthreads();
    int Ktot = sKtot;
    for (int jj = tid; jj < SEL_TOT; jj += 128) {
        int w = jj >> 5, b = jj & 31;
        unsigned below = (b == 0) ? 0u : (kw[w] & (0xFFFFFFFFu >> (32 - b)));
        int kr = wpfx[w] + __popc(below);
        bool kp = (kw[w] >> b) & 1u;
        if (kp) {
            if (kr < 100) sel[kr] = jj;
        } else if (Ktot < 100) {
            int pos = Ktot + (jj - kr);
            if (pos < 100) sel[pos] = jj;
        }
    }
    __syncthreads();
    if (tid < 100) {
        int jj = sel[tid];
        int w = jj >> 5, b = jj & 31;
        bool kp = (kw[w] >> b) & 1u;
        float vy1 = loc[0], vx1 = loc[1], vy2 = loc[2], vx2 = loc[3];
        float oh = loc[4], ow = loc[5];
        float sy = oh / fmaxf(vy2 - vy1, 1e-6f);
        float sx = ow / fmaxf(vx2 - vx1, 1e-6f);
        float4 bx = g_srtBox[jj];
        if (tid * 4 + 3 < out_size) {
            out[tid * 4 + 0] = (bx.x - vy1) * sy;
            out[tid * 4 + 1] = (bx.y - vx1) * sx;
            out[tid * 4 + 2] = (bx.z - vy1) * sy;
            out[tid * 4 + 3] = (bx.w - vx1) * sx;
        }
        if (400 + tid < out_size) out[400 + tid] = (float)g_srtCls[jj];
        if (500 + tid < out_size) out[500 + tid] = kp ? g_srtScore[jj] : 0.0f;
    }
}

// ---------------- host launcher --------------------------------------------
extern "C" void kernel_launch(void* const* d_in, const int* in_sizes, int n_in,
                              void* d_out, int out_size) {
    const float *cls[5] = {0, 0, 0, 0, 0};
    const float *reg[5] = {0, 0, 0, 0, 0};
    const float *loc = 0;
    for (int i = 0; i < n_in; i++) {
        switch (in_sizes[i]) {
            case 5242880: cls[0] = (const float*)d_in[i]; break;
            case 1310720: cls[1] = (const float*)d_in[i]; break;
            case 327680:  cls[2] = (const float*)d_in[i]; break;
            case 81920:   cls[3] = (const float*)d_in[i]; break;
            case 20480:   cls[4] = (const float*)d_in[i]; break;
            case 262144:  reg[0] = (const float*)d_in[i]; break;
            case 65536:   reg[1] = (const float*)d_in[i]; break;
            case 16384:   reg[2] = (const float*)d_in[i]; break;
            case 4096:    reg[3] = (const float*)d_in[i]; break;
            case 1024:    reg[4] = (const float*)d_in[i]; break;
            case 6:       loc    = (const float*)d_in[i]; break;
            default: break;
        }
    }
    static int smemSet = 0;
    if (!smemSet) {
        cudaFuncSetAttribute(nmsKernel, cudaFuncAttributeMaxDynamicSharedMemorySize,
                             128 * MPITCH * 4);
        smemSet = 1;
    }
    int blocks = (N_TOT * 32 + 255) / 256;
    scoreKernel<<<blocks, 256>>>(cls[0], cls[1], cls[2], cls[3], cls[4]);
    pivotKernel<<<5, 256>>>();
    fillKernel<<<341, 256>>>(reg[0], reg[1], reg[2], reg[3], reg[4], loc);
    dim3 rg(5, EQCAP / RTILE);
    refineKernel<<<rg, 256>>>(reg[0], reg[1], reg[2], reg[3], reg[4], loc);
    rankKernel<<<68, 512>>>();
    dim3 mg(17, 17);
    matrixKernel<<<mg, 128>>>();
    nmsKernel<<<JTILES, 128, 128 * MPITCH * 4>>>((float*)d_out, loc, out_size);
}

// round 13
// speedup vs baseline: 1.2192x; 1.2192x over previous
#include <cuda_runtime.h>
#include <math.h>

#define N_TOT    87296
#define SEL_TOT  4256
#define SEL_PAD  4352
#define SEL_PAD2 4352
#define WW       136
#define JTILES   34
#define KSLAB    256
#define NSLAB    17
#define EQCAP    4096
#define HBINS    8192
#define MPITCH   137
#define RTILE    64

// ---------------- scratch (device globals; no allocations) -----------------
__device__ float    g_key[N_TOT];
__device__ int      g_cls[N_TOT];
__device__ float    g_selKey[SEL_TOT];
__device__ int      g_selCls[SEL_TOT];
__device__ int      g_selTie[SEL_TOT];
__device__ float4   g_selBox[SEL_TOT];
__device__ float    g_srtScore[SEL_PAD];
__device__ int      g_srtCls[SEL_PAD];
__device__ int      g_srtValid[SEL_PAD];
__device__ float4   g_srtBox[SEL_PAD];
__device__ unsigned long long g_bufA[N_TOT];
__device__ unsigned g_hist[5 * HBINS];          // zeroed at end of finalKernel
__device__ unsigned g_b13[5];
__device__ int      g_need[5];
__device__ int      g_cg[5];                    // zeroed at end of finalKernel
__device__ int      g_cntTie[5];                // zeroed at end of finalKernel
__device__ unsigned g_Mt[(size_t)WW * SEL_PAD2]; // column-major: Mt[w][j]
__device__ unsigned g_keep[2][WW];
__device__ unsigned g_keepOut[WW];
__device__ unsigned g_changeArr[16];
__device__ unsigned g_barCount = 0;
__device__ unsigned g_barGen   = 0;             // monotonic across replays

__device__ __forceinline__ unsigned fflip(float f) {
    unsigned u = __float_as_uint(f);
    return (u & 0x80000000u) ? ~u : (u | 0x80000000u);
}

__constant__ int c_OFF[5]  = {0, 65536, 81920, 86016, 87040};
__constant__ int c_SOFF[5] = {0, 1000, 2000, 3000, 4000};
__constant__ int c_K[5]    = {1000, 1000, 1000, 1000, 256};

// ------- 1. per-anchor class max + fused histogram (warp per anchor) -------
__global__ void scoreKernel(const float* __restrict__ c0, const float* __restrict__ c1,
                            const float* __restrict__ c2, const float* __restrict__ c3,
                            const float* __restrict__ c4) {
    int warp = (blockIdx.x * blockDim.x + threadIdx.x) >> 5;
    int lane = threadIdx.x & 31;
    if (warp >= N_TOT) return;
    int off, lvl;
    const float* base;
    if      (warp < 65536) { off = 0;     base = c0; lvl = 0; }
    else if (warp < 81920) { off = 65536; base = c1; lvl = 1; }
    else if (warp < 86016) { off = 81920; base = c2; lvl = 2; }
    else if (warp < 87040) { off = 86016; base = c3; lvl = 3; }
    else                   { off = 87040; base = c4; lvl = 4; }
    int a = warp - off;
    float v = -1e30f; int bi = 1 << 20;
    if (lane < 20) {
        const float4* p4 = reinterpret_cast<const float4*>(base + (size_t)a * 80);
        float4 q = p4[lane];
        int cb = lane * 4;
        v = q.x; bi = cb;
        if (q.y > v) { v = q.y; bi = cb + 1; }
        if (q.z > v) { v = q.z; bi = cb + 2; }
        if (q.w > v) { v = q.w; bi = cb + 3; }
    }
    for (int o = 16; o; o >>= 1) {
        float ov = __shfl_down_sync(0xffffffffu, v, o);
        int   oi = __shfl_down_sync(0xffffffffu, bi, o);
        if (ov > v || (ov == v && oi < bi)) { v = ov; bi = oi; }
    }
    if (lane == 0) {
        float ps = 1.0f / (1.0f + expf(-v));
        float kf = (ps > 0.05f) ? ps : -1.0f;
        g_key[warp] = kf;
        g_cls[warp] = bi + 1;
        atomicAdd(&g_hist[lvl * HBINS + (fflip(kf) >> 19)], 1u);  // RED, no return
    }
}

// ------- 2a. pivot per level (5 blocks, fully parallel scans) --------------
__global__ void pivotKernel() {
    int lvl = blockIdx.x, tid = threadIdx.x;
    __shared__ unsigned sfx[256], coarse[256];
    __shared__ int sCb, sAcc;
    const unsigned* H = g_hist + lvl * HBINS;
    unsigned s = 0;
    #pragma unroll 8
    for (int j = 0; j < 32; j++) s += H[tid * 32 + j];
    coarse[tid] = s;
    sfx[tid] = s;
    __syncthreads();
    for (int d = 1; d < 256; d <<= 1) {              // suffix scan (Hillis-Steele)
        unsigned v = (tid + d < 256) ? sfx[tid + d] : 0u;
        __syncthreads();
        sfx[tid] += v;
        __syncthreads();
    }
    unsigned k = (unsigned)c_K[lvl];
    unsigned incl = sfx[tid], excl = incl - coarse[tid];
    if (incl >= k && excl < k) { sCb = tid; sAcc = (int)excl; }
    __syncthreads();
    int cb = sCb;
    unsigned kk = k - (unsigned)sAcc;
    if (tid < 32) {
        unsigned hv = H[cb * 32 + tid];
        unsigned x = hv;
        #pragma unroll
        for (int d = 1; d < 32; d <<= 1) {
            unsigned y = __shfl_down_sync(0xffffffffu, x, d);
            if (tid + d < 32) x += y;
        }
        unsigned excl2 = x - hv;
        if (x >= kk && excl2 < kk) {
            g_b13[lvl]  = (unsigned)(cb * 32 + tid);
            g_need[lvl] = (int)(kk - excl2);
        }
    }
}

// ---------------- common: write one selected candidate ---------------------
__device__ __forceinline__ void writeSel(int slot, float kf, int gidx, int lvl, int i,
                                         const float* __restrict__ reg,
                                         float l0, float l1, float l2, float l3) {
    g_selKey[slot] = kf;
    g_selCls[slot] = g_cls[gidx];
    g_selTie[slot] = (lvl << 17) | i;
    float b0 = reg[(size_t)i * 4 + 0], b1 = reg[(size_t)i * 4 + 1];
    float b2 = reg[(size_t)i * 4 + 2], b3 = reg[(size_t)i * 4 + 3];
    g_selBox[slot] = make_float4(fmaxf(b0, l0), fmaxf(b1, l1),
                                 fminf(b2, l2), fminf(b3, l3));
}

// ------- 2b. fill winners + tie buffer (341 blocks) ------------------------
__global__ void fillKernel(const float* __restrict__ r0, const float* __restrict__ r1,
                           const float* __restrict__ r2, const float* __restrict__ r3,
                           const float* __restrict__ r4, const float* __restrict__ loc) {
    int b = blockIdx.x, lvl, start;
    if      (b < 256) { lvl = 0; start = b * 256; }
    else if (b < 320) { lvl = 1; start = 65536 + (b - 256) * 256; }
    else if (b < 336) { lvl = 2; start = 81920 + (b - 320) * 256; }
    else if (b < 340) { lvl = 3; start = 86016 + (b - 336) * 256; }
    else              { lvl = 4; start = 87040; }
    unsigned b13 = g_b13[lvl];
    int off = c_OFF[lvl], sbase = c_SOFF[lvl];
    const float* reg = (lvl == 0) ? r0 : (lvl == 1) ? r1 : (lvl == 2) ? r2 : (lvl == 3) ? r3 : r4;
    float l0 = loc[0], l1 = loc[1], l2 = loc[2], l3 = loc[3];
    int tid = threadIdx.x, lane = tid & 31;
    int idx = start + tid;
    float kf = g_key[idx];
    unsigned u = fflip(kf);
    unsigned top = u >> 19;
    bool win = top > b13;
    bool tie = top == b13;
    unsigned wb = __ballot_sync(0xffffffffu, win);
    if (wb) {
        int ld = __ffs(wb) - 1; int bs = 0;
        if (lane == ld) bs = atomicAdd(&g_cg[lvl], __popc(wb));
        bs = __shfl_sync(0xffffffffu, bs, ld);
        if (win) {
            int slot = sbase + bs + __popc(wb & ((1u << lane) - 1u));
            writeSel(slot, kf, idx, lvl, idx - off, reg, l0, l1, l2, l3);
        }
    }
    unsigned tb = __ballot_sync(0xffffffffu, tie);
    if (tb) {
        int ld = __ffs(tb) - 1; int bs = 0;
        if (lane == ld) bs = atomicAdd(&g_cntTie[lvl], __popc(tb));
        bs = __shfl_sync(0xffffffffu, bs, ld);
        if (tie) {
            int t = bs + __popc(tb & ((1u << lane) - 1u));
            g_bufA[off + t] = ((unsigned long long)u << 32) | (unsigned)(idx - off);
        }
    }
}

// ------- 2c. tie resolution by direct rank (5 x 64 blocks, 4 thr/elem) -----
__global__ void refineKernel(const float* __restrict__ r0, const float* __restrict__ r1,
                             const float* __restrict__ r2, const float* __restrict__ r3,
                             const float* __restrict__ r4, const float* __restrict__ loc) {
    int lvl = blockIdx.x;
    int tile = blockIdx.y;
    int tid = threadIdx.x;
    int need = g_need[lvl];
    int m = g_cntTie[lvl]; if (m > EQCAP) m = EQCAP;
    int lo = tile * RTILE;
    if (lo >= m || need <= 0) return;
    int off = c_OFF[lvl], sbase = c_SOFF[lvl];
    const float* reg = (lvl == 0) ? r0 : (lvl == 1) ? r1 : (lvl == 2) ? r2 : (lvl == 3) ? r3 : r4;
    float l0 = loc[0], l1 = loc[1], l2 = loc[2], l3 = loc[3];
    __shared__ unsigned long long ee[EQCAP];
    __shared__ int part[256];
    for (int i = tid; i < m; i += 256) {
        unsigned long long e = g_bufA[off + i];
        unsigned u = (unsigned)(e >> 32);
        unsigned idx = (unsigned)e;
        ee[i] = ((unsigned long long)u << 32) | (0xFFFFFFFFu - idx);  // value desc, idx asc
    }
    __syncthreads();
    int e_i = lo + (tid & 63);
    int seg = tid >> 6;                         // 0..3
    int mq = (m + 3) >> 2;
    int cnt = 0;
    if (e_i < m) {
        unsigned long long mine = ee[e_i];
        int a = seg * mq, bq = a + mq; if (bq > m) bq = m;
        for (int q = a; q < bq; q++) cnt += (ee[q] > mine) ? 1 : 0;
    }
    part[tid] = cnt;
    __syncthreads();
    if (seg == 0 && e_i < m) {
        int rank = part[tid] + part[tid + 64] + part[tid + 128] + part[tid + 192];
        if (rank < need) {                      // exact top_k tie rule; order irrelevant
            int idx = (int)(0xFFFFFFFFu - (unsigned)ee[e_i]);
            int slot = sbase + atomicAdd(&g_cg[lvl], 1);
            writeSel(slot, g_key[off + idx], off + idx, lvl, idx, reg, l0, l1, l2, l3);
        }
    }
}

// ---------------- 3. rank-sort, 8 threads per element (68 blocks) ----------
__global__ void rankKernel() {
    __shared__ unsigned long long sk[SEL_TOT];
    __shared__ int part[512];
    int tid = threadIdx.x;
    for (int i = tid; i < SEL_TOT; i += 512) {
        float kf = g_selKey[i];
        float ss = (kf > 0.0f) ? kf : 0.0f;
        unsigned tie = (unsigned)g_selTie[i];
        sk[i] = ((unsigned long long)fflip(ss) << 20) |
                (unsigned long long)(0xFFFFFu - tie);
    }
    __syncthreads();
    int e = blockIdx.x * 64 + (tid & 63);
    int seg = tid >> 6;                       // 0..7, 532 elements each
    int cnt = 0;
    if (e < SEL_TOT) {
        unsigned long long mine = sk[e];
        int lo = seg * 532, hi = lo + 532;    // 8*532 = 4256
        #pragma unroll 4
        for (int i = lo; i < hi; i++) cnt += (sk[i] > mine) ? 1 : 0;
    }
    part[tid] = cnt;
    __syncthreads();
    if (seg == 0 && e < SEL_TOT) {
        int rank = 0;
        #pragma unroll
        for (int s = 0; s < 8; s++) rank += part[(tid & 63) + s * 64];
        float kf = g_selKey[e];
        g_srtScore[rank] = (kf > 0.0f) ? kf : 0.0f;
        g_srtValid[rank] = (kf > 0.0f) ? 1 : 0;
        g_srtCls[rank]   = g_selCls[e];
        g_srtBox[rank]   = g_selBox[e];
    }
    if (blockIdx.x == 0 && tid < 16) g_changeArr[tid] = 0u;
}

// ------- 4. suppression bitmask, column-major (bit k of word w, col j) ------
__global__ void matrixKernel() {
    int jbase = blockIdx.x * 128;
    int kbase = blockIdx.y * KSLAB;
    if (kbase >= jbase + 128) return;
    __shared__ float4 kb[KSLAB];
    __shared__ float  ka[KSLAB];
    int tid = threadIdx.x;
    for (int t = tid; t < KSLAB; t += 128) {
        int kk = kbase + t;
        float4 b = (kk < SEL_TOT) ? g_srtBox[kk] : make_float4(0.f, 0.f, 0.f, 0.f);
        kb[t] = b;
        ka[t] = fmaxf(b.z - b.x, 0.f) * fmaxf(b.w - b.y, 0.f);
    }
    __syncthreads();
    int j = jbase + tid;
    if (j >= SEL_TOT) return;
    float4 bj = g_srtBox[j];
    float aj = fmaxf(bj.z - bj.x, 0.f) * fmaxf(bj.w - bj.y, 0.f);
    int w0 = kbase >> 5;
    for (int wi = 0; wi < KSLAB / 32; wi++) {
        unsigned word = 0u;
        int tb = wi * 32;
        if (kbase + tb < j) {
            #pragma unroll
            for (int t = 0; t < 32; t++) {
                int k = kbase + tb + t;
                float4 bk = kb[tb + t];
                float iy1 = fmaxf(bk.x, bj.x), ix1 = fmaxf(bk.y, bj.y);
                float iy2 = fminf(bk.z, bj.z), ix2 = fminf(bk.w, bj.w);
                float inter = fmaxf(iy2 - iy1, 0.f) * fmaxf(ix2 - ix1, 0.f);
                float uni = aj + ka[tb + t] - inter;
                bool bit = (k < j) && (inter > 0.5f * fmaxf(uni, 1e-9f));
                if (bit) word |= (1u << t);
            }
        }
        g_Mt[(size_t)(w0 + wi) * SEL_PAD2 + j] = word;
    }
}

// -------- 5. all 16 Jacobi iterations, M cached in smem (grid barrier) -----
// hard-spin barrier: no nanosleep — detection latency ~1 L2 round trip
__device__ __forceinline__ void gridBarrier(unsigned nb) {
    __threadfence();
    __syncthreads();
    if (threadIdx.x == 0) {
        unsigned my = __ldcg(&g_barGen);
        if (atomicAdd(&g_barCount, 1u) == nb - 1u) {
            atomicExch(&g_barCount, 0u);
            __threadfence();
            atomicAdd(&g_barGen, 1u);
        } else {
            while (__ldcg(&g_barGen) == my) { }
        }
    }
    __syncthreads();
}

extern __shared__ unsigned sMdyn[];              // 128 * MPITCH words
__global__ void nmsKernel() {
    __shared__ unsigned sK[WW];
    int tid = threadIdx.x;
    int j = blockIdx.x * 128 + tid;
    int lane = tid & 31;
    int wj = j >> 5;
    int wtop = (j > 0 && j < SEL_TOT) ? (((j - 1) >> 5) + 1) : 0;
    unsigned* mrow = sMdyn + tid * MPITCH;
    for (int w = 0; w < WW; w++)                  // coalesced across tid
        mrow[w] = g_Mt[(size_t)w * SEL_PAD2 + j];
    unsigned lastBal = 0xFFFFFFFFu;

    for (int t = 0; t < 16; t++) {
        if (t == 0) {
            for (int w = tid; w < WW; w += 128) sK[w] = 0xFFFFFFFFu;
        } else {
            const unsigned* src = g_keep[(t - 1) & 1];
            for (int w = tid; w < WW; w += 128) sK[w] = __ldcg(&src[w]);
        }
        __syncthreads();
        unsigned acc = 0u;
        #pragma unroll 4
        for (int w = 0; w < wtop; w++) acc |= mrow[w] & sK[w];
        bool keepNew = (acc == 0u);
        unsigned bal = __ballot_sync(0xffffffffu, keepNew);
        unsigned oldw = sK[wj];
        if (lane == 0) {
            __stcg(&g_keep[t & 1][wj], bal);
            if (bal != oldw) atomicOr(&g_changeArr[t], 1u);
        }
        lastBal = bal;
        gridBarrier(JTILES);
        unsigned chg = __ldcg(&g_changeArr[t]);
        __syncthreads();
        if (chg == 0u) break;
    }
    if (lane == 0) __stcg(&g_keepOut[wj], lastBal);
}

// ------------- 6. final top-100 (block 0) + parallel state reset -----------
__global__ void finalKernel(float* __restrict__ out, const float* __restrict__ loc,
                            int out_size) {
    int tid = threadIdx.x;
    // all blocks: reset a slice of state for the next execution
    {
        int total = 5 * HBINS;
        int per = (total + gridDim.x - 1) / gridDim.x;
        int lo = blockIdx.x * per, hi = lo + per; if (hi > total) hi = total;
        for (int i = lo + tid; i < hi; i += blockDim.x) g_hist[i] = 0u;
    }
    if (blockIdx.x != 0) return;
    if (tid < 5) { g_cg[tid] = 0; g_cntTie[tid] = 0; }

    __shared__ unsigned kw[WW];
    __shared__ int wpfx[WW + 1];
    __shared__ int sel[100];
    __shared__ int sKtot;

    for (int w = tid; w < WW; w += blockDim.x) {
        unsigned vb = 0u;
        int base = w * 32;
        #pragma unroll 4
        for (int b = 0; b < 32; b++) {
            int j = base + b;
            if (j < SEL_TOT && g_srtValid[j]) vb |= (1u << b);
        }
        kw[w] = g_keepOut[w] & vb;
    }
    __syncthreads();
    if (tid == 0) {
        int acc = 0;
        for (int w = 0; w < WW; w++) { wpfx[w] = acc; acc += __popc(kw[w]); }
        wpfx[WW] = acc;
        sKtot = acc;
    }
    __syncthreads();
    int Ktot = sKtot;
    for (int j = tid; j < SEL_TOT; j += blockDim.x) {
        int w = j >> 5, b = j & 31;
        unsigned below = (b == 0) ? 0u : (kw[w] & (0xFFFFFFFFu >> (32 - b)));
        int kr = wpfx[w] + __popc(below);
        bool kp = (kw[w] >> b) & 1u;
        if (kp) {
            if (kr < 100) sel[kr] = j;
        } else if (Ktot < 100) {
            int pos = Ktot + (j - kr);
            if (pos < 100) sel[pos] = j;
        }
    }
    __syncthreads();
    if (tid < 100) {
        int j = sel[tid];
        int w = j >> 5, b = j & 31;
        bool kp = (kw[w] >> b) & 1u;
        float vy1 = loc[0], vx1 = loc[1], vy2 = loc[2], vx2 = loc[3];
        float oh = loc[4], ow = loc[5];
        float sy = oh / fmaxf(vy2 - vy1, 1e-6f);
        float sx = ow / fmaxf(vx2 - vx1, 1e-6f);
        float4 bx = g_srtBox[j];
        if (tid * 4 + 3 < out_size) {
            out[tid * 4 + 0] = (bx.x - vy1) * sy;
            out[tid * 4 + 1] = (bx.y - vx1) * sx;
            out[tid * 4 + 2] = (bx.z - vy1) * sy;
            out[tid * 4 + 3] = (bx.w - vx1) * sx;
        }
        if (400 + tid < out_size) out[400 + tid] = (float)g_srtCls[j];
        if (500 + tid < out_size) out[500 + tid] = kp ? g_srtScore[j] : 0.0f;
    }
}

// ---------------- host launcher --------------------------------------------
extern "C" void kernel_launch(void* const* d_in, const int* in_sizes, int n_in,
                              void* d_out, int out_size) {
    const float *cls[5] = {0, 0, 0, 0, 0};
    const float *reg[5] = {0, 0, 0, 0, 0};
    const float *loc = 0;
    for (int i = 0; i < n_in; i++) {
        switch (in_sizes[i]) {
            case 5242880: cls[0] = (const float*)d_in[i]; break;
            case 1310720: cls[1] = (const float*)d_in[i]; break;
            case 327680:  cls[2] = (const float*)d_in[i]; break;
            case 81920:   cls[3] = (const float*)d_in[i]; break;
            case 20480:   cls[4] = (const float*)d_in[i]; break;
            case 262144:  reg[0] = (const float*)d_in[i]; break;
            case 65536:   reg[1] = (const float*)d_in[i]; break;
            case 16384:   reg[2] = (const float*)d_in[i]; break;
            case 4096:    reg[3] = (const float*)d_in[i]; break;
            case 1024:    reg[4] = (const float*)d_in[i]; break;
            case 6:       loc    = (const float*)d_in[i]; break;
            default: break;
        }
    }
    static int smemSet = 0;
    if (!smemSet) {
        cudaFuncSetAttribute(nmsKernel, cudaFuncAttributeMaxDynamicSharedMemorySize,
                             128 * MPITCH * 4);
        smemSet = 1;
    }
    int blocks = (N_TOT * 32 + 255) / 256;
    scoreKernel<<<blocks, 256>>>(cls[0], cls[1], cls[2], cls[3], cls[4]);
    pivotKernel<<<5, 256>>>();
    fillKernel<<<341, 256>>>(reg[0], reg[1], reg[2], reg[3], reg[4], loc);
    dim3 rg(5, EQCAP / RTILE);
    refineKernel<<<rg, 256>>>(reg[0], reg[1], reg[2], reg[3], reg[4], loc);
    rankKernel<<<68, 512>>>();
    dim3 mg(JTILES, NSLAB);
    matrixKernel<<<mg, 128>>>();
    nmsKernel<<<JTILES, 128, 128 * MPITCH * 4>>>();
    finalKernel<<<17, 256>>>((float*)d_out, loc, out_size);
}

// round 16
// speedup vs baseline: 1.2234x; 1.0035x over previous
#include <cuda_runtime.h>
#include <math.h>

#define N_TOT    87296
#define SEL_TOT  4256
#define SEL_PAD  4352
#define SEL_PAD2 4352
#define WW       136
#define JTILES   34
#define KSLAB    128
#define NSLAB    34
#define EQCAP    4096
#define HBINS    8192
#define MPITCH   137
#define RTILE    64

// ---------------- scratch (device globals; no allocations) -----------------
__device__ float    g_key[N_TOT];
__device__ int      g_cls[N_TOT];
__device__ float    g_selKey[SEL_TOT];
__device__ int      g_selCls[SEL_TOT];
__device__ int      g_selTie[SEL_TOT];
__device__ float4   g_selBox[SEL_TOT];
__device__ float    g_srtScore[SEL_PAD];
__device__ int      g_srtCls[SEL_PAD];
__device__ int      g_srtValid[SEL_PAD];
__device__ float4   g_srtBox[SEL_PAD];
__device__ unsigned long long g_bufA[N_TOT];
__device__ unsigned g_hist[5 * HBINS];          // zeroed at end of finalKernel
__device__ unsigned g_b13[5];
__device__ int      g_need[5];
__device__ int      g_cg[5];                    // zeroed at end of finalKernel
__device__ int      g_cntTie[5];                // zeroed at end of finalKernel
__device__ unsigned g_Mt[(size_t)WW * SEL_PAD2]; // column-major: Mt[w][j]
__device__ unsigned g_keep[2][WW];
__device__ unsigned g_keepOut[WW];
__device__ unsigned g_changeArr[16];
__device__ unsigned g_barCount = 0;
__device__ unsigned g_barGen   = 0;             // monotonic across replays

__device__ __forceinline__ unsigned fflip(float f) {
    unsigned u = __float_as_uint(f);
    return (u & 0x80000000u) ? ~u : (u | 0x80000000u);
}

__constant__ int c_OFF[5]  = {0, 65536, 81920, 86016, 87040};
__constant__ int c_SOFF[5] = {0, 1000, 2000, 3000, 4000};
__constant__ int c_K[5]    = {1000, 1000, 1000, 1000, 256};

// ------- 1. per-anchor class max + fused histogram (warp per anchor) -------
__global__ void scoreKernel(const float* __restrict__ c0, const float* __restrict__ c1,
                            const float* __restrict__ c2, const float* __restrict__ c3,
                            const float* __restrict__ c4) {
    int warp = (blockIdx.x * blockDim.x + threadIdx.x) >> 5;
    int lane = threadIdx.x & 31;
    if (warp >= N_TOT) return;
    int off, lvl;
    const float* base;
    if      (warp < 65536) { off = 0;     base = c0; lvl = 0; }
    else if (warp < 81920) { off = 65536; base = c1; lvl = 1; }
    else if (warp < 86016) { off = 81920; base = c2; lvl = 2; }
    else if (warp < 87040) { off = 86016; base = c3; lvl = 3; }
    else                   { off = 87040; base = c4; lvl = 4; }
    int a = warp - off;
    float v = -1e30f; int bi = 1 << 20;
    if (lane < 20) {
        const float4* p4 = reinterpret_cast<const float4*>(base + (size_t)a * 80);
        float4 q = p4[lane];
        int cb = lane * 4;
        v = q.x; bi = cb;
        if (q.y > v) { v = q.y; bi = cb + 1; }
        if (q.z > v) { v = q.z; bi = cb + 2; }
        if (q.w > v) { v = q.w; bi = cb + 3; }
    }
    for (int o = 16; o; o >>= 1) {
        float ov = __shfl_down_sync(0xffffffffu, v, o);
        int   oi = __shfl_down_sync(0xffffffffu, bi, o);
        if (ov > v || (ov == v && oi < bi)) { v = ov; bi = oi; }
    }
    if (lane == 0) {
        float ps = 1.0f / (1.0f + expf(-v));
        float kf = (ps > 0.05f) ? ps : -1.0f;
        g_key[warp] = kf;
        g_cls[warp] = bi + 1;
        atomicAdd(&g_hist[lvl * HBINS + (fflip(kf) >> 19)], 1u);  // RED, no return
    }
}

// ------- 2a. pivot per level (5 blocks, fully parallel scans) --------------
__global__ void pivotKernel() {
    int lvl = blockIdx.x, tid = threadIdx.x;
    __shared__ unsigned sfx[256], coarse[256];
    __shared__ int sCb, sAcc;
    const unsigned* H = g_hist + lvl * HBINS;
    unsigned s = 0;
    #pragma unroll 8
    for (int j = 0; j < 32; j++) s += H[tid * 32 + j];
    coarse[tid] = s;
    sfx[tid] = s;
    __syncthreads();
    for (int d = 1; d < 256; d <<= 1) {              // suffix scan (Hillis-Steele)
        unsigned v = (tid + d < 256) ? sfx[tid + d] : 0u;
        __syncthreads();
        sfx[tid] += v;
        __syncthreads();
    }
    unsigned k = (unsigned)c_K[lvl];
    unsigned incl = sfx[tid], excl = incl - coarse[tid];
    if (incl >= k && excl < k) { sCb = tid; sAcc = (int)excl; }
    __syncthreads();
    int cb = sCb;
    unsigned kk = k - (unsigned)sAcc;
    if (tid < 32) {
        unsigned hv = H[cb * 32 + tid];
        unsigned x = hv;
        #pragma unroll
        for (int d = 1; d < 32; d <<= 1) {
            unsigned y = __shfl_down_sync(0xffffffffu, x, d);
            if (tid + d < 32) x += y;
        }
        unsigned excl2 = x - hv;
        if (x >= kk && excl2 < kk) {
            g_b13[lvl]  = (unsigned)(cb * 32 + tid);
            g_need[lvl] = (int)(kk - excl2);
        }
    }
}

// ---------------- common: write one selected candidate ---------------------
__device__ __forceinline__ void writeSel(int slot, float kf, int gidx, int lvl, int i,
                                         const float* __restrict__ reg,
                                         float l0, float l1, float l2, float l3) {
    g_selKey[slot] = kf;
    g_selCls[slot] = g_cls[gidx];
    g_selTie[slot] = (lvl << 17) | i;
    float b0 = reg[(size_t)i * 4 + 0], b1 = reg[(size_t)i * 4 + 1];
    float b2 = reg[(size_t)i * 4 + 2], b3 = reg[(size_t)i * 4 + 3];
    g_selBox[slot] = make_float4(fmaxf(b0, l0), fmaxf(b1, l1),
                                 fminf(b2, l2), fminf(b3, l3));
}

// ------- 2b. fill winners + tie buffer (341 blocks) ------------------------
__global__ void fillKernel(const float* __restrict__ r0, const float* __restrict__ r1,
                           const float* __restrict__ r2, const float* __restrict__ r3,
                           const float* __restrict__ r4, const float* __restrict__ loc) {
    int b = blockIdx.x, lvl, start;
    if      (b < 256) { lvl = 0; start = b * 256; }
    else if (b < 320) { lvl = 1; start = 65536 + (b - 256) * 256; }
    else if (b < 336) { lvl = 2; start = 81920 + (b - 320) * 256; }
    else if (b < 340) { lvl = 3; start = 86016 + (b - 336) * 256; }
    else              { lvl = 4; start = 87040; }
    unsigned b13 = g_b13[lvl];
    int off = c_OFF[lvl], sbase = c_SOFF[lvl];
    const float* reg = (lvl == 0) ? r0 : (lvl == 1) ? r1 : (lvl == 2) ? r2 : (lvl == 3) ? r3 : r4;
    float l0 = loc[0], l1 = loc[1], l2 = loc[2], l3 = loc[3];
    int tid = threadIdx.x, lane = tid & 31;
    int idx = start + tid;
    float kf = g_key[idx];
    unsigned u = fflip(kf);
    unsigned top = u >> 19;
    bool win = top > b13;
    bool tie = top == b13;
    unsigned wb = __ballot_sync(0xffffffffu, win);
    if (wb) {
        int ld = __ffs(wb) - 1; int bs = 0;
        if (lane == ld) bs = atomicAdd(&g_cg[lvl], __popc(wb));
        bs = __shfl_sync(0xffffffffu, bs, ld);
        if (win) {
            int slot = sbase + bs + __popc(wb & ((1u << lane) - 1u));
            writeSel(slot, kf, idx, lvl, idx - off, reg, l0, l1, l2, l3);
        }
    }
    unsigned tb = __ballot_sync(0xffffffffu, tie);
    if (tb) {
        int ld = __ffs(tb) - 1; int bs = 0;
        if (lane == ld) bs = atomicAdd(&g_cntTie[lvl], __popc(tb));
        bs = __shfl_sync(0xffffffffu, bs, ld);
        if (tie) {
            int t = bs + __popc(tb & ((1u << lane) - 1u));
            g_bufA[off + t] = ((unsigned long long)u << 32) | (unsigned)(idx - off);
        }
    }
}

// ------- 2c. tie resolution by direct rank (5 x 64 blocks, 4 thr/elem) -----
__global__ void refineKernel(const float* __restrict__ r0, const float* __restrict__ r1,
                             const float* __restrict__ r2, const float* __restrict__ r3,
                             const float* __restrict__ r4, const float* __restrict__ loc) {
    int lvl = blockIdx.x;
    int tile = blockIdx.y;
    int tid = threadIdx.x;
    int need = g_need[lvl];
    int m = g_cntTie[lvl]; if (m > EQCAP) m = EQCAP;
    int lo = tile * RTILE;
    if (lo >= m || need <= 0) return;
    int off = c_OFF[lvl], sbase = c_SOFF[lvl];
    const float* reg = (lvl == 0) ? r0 : (lvl == 1) ? r1 : (lvl == 2) ? r2 : (lvl == 3) ? r3 : r4;
    float l0 = loc[0], l1 = loc[1], l2 = loc[2], l3 = loc[3];
    __shared__ unsigned long long ee[EQCAP];
    __shared__ int part[256];
    for (int i = tid; i < m; i += 256) {
        unsigned long long e = g_bufA[off + i];
        unsigned u = (unsigned)(e >> 32);
        unsigned idx = (unsigned)e;
        ee[i] = ((unsigned long long)u << 32) | (0xFFFFFFFFu - idx);  // value desc, idx asc
    }
    __syncthreads();
    int e_i = lo + (tid & 63);
    int seg = tid >> 6;                         // 0..3
    int mq = (m + 3) >> 2;
    int cnt = 0;
    if (e_i < m) {
        unsigned long long mine = ee[e_i];
        int a = seg * mq, bq = a + mq; if (bq > m) bq = m;
        for (int q = a; q < bq; q++) cnt += (ee[q] > mine) ? 1 : 0;
    }
    part[tid] = cnt;
    __syncthreads();
    if (seg == 0 && e_i < m) {
        int rank = part[tid] + part[tid + 64] + part[tid + 128] + part[tid + 192];
        if (rank < need) {                      // exact top_k tie rule; order irrelevant
            int idx = (int)(0xFFFFFFFFu - (unsigned)ee[e_i]);
            int slot = sbase + atomicAdd(&g_cg[lvl], 1);
            writeSel(slot, g_key[off + idx], off + idx, lvl, idx, reg, l0, l1, l2, l3);
        }
    }
}

// ---------------- 3. rank-sort, 8 threads per element (68 blocks) ----------
__global__ void rankKernel() {
    __shared__ unsigned long long sk[SEL_TOT];
    __shared__ int part[512];
    int tid = threadIdx.x;
    for (int i = tid; i < SEL_TOT; i += 512) {
        float kf = g_selKey[i];
        float ss = (kf > 0.0f) ? kf : 0.0f;
        unsigned tie = (unsigned)g_selTie[i];
        sk[i] = ((unsigned long long)fflip(ss) << 20) |
                (unsigned long long)(0xFFFFFu - tie);
    }
    __syncthreads();
    int e = blockIdx.x * 64 + (tid & 63);
    int seg = tid >> 6;                       // 0..7, 532 elements each
    int cnt = 0;
    if (e < SEL_TOT) {
        unsigned long long mine = sk[e];
        int lo = seg * 532, hi = lo + 532;    // 8*532 = 4256
        #pragma unroll 4
        for (int i = lo; i < hi; i++) cnt += (sk[i] > mine) ? 1 : 0;
    }
    part[tid] = cnt;
    __syncthreads();
    if (seg == 0 && e < SEL_TOT) {
        int rank = 0;
        #pragma unroll
        for (int s = 0; s < 8; s++) rank += part[(tid & 63) + s * 64];
        float kf = g_selKey[e];
        g_srtScore[rank] = (kf > 0.0f) ? kf : 0.0f;
        g_srtValid[rank] = (kf > 0.0f) ? 1 : 0;
        g_srtCls[rank]   = g_selCls[e];
        g_srtBox[rank]   = g_selBox[e];
    }
    if (blockIdx.x == 0 && tid < 16) g_changeArr[tid] = 0u;
}

// ------- 4. suppression bitmask, column-major (bit k of word w, col j) ------
__global__ void matrixKernel() {
    int jbase = blockIdx.x * 128;
    int kbase = blockIdx.y * KSLAB;
    if (kbase >= jbase + 128) return;
    __shared__ float4 kb[KSLAB];
    __shared__ float  ka[KSLAB];
    int tid = threadIdx.x;
    for (int t = tid; t < KSLAB; t += 128) {
        int kk = kbase + t;
        float4 b = (kk < SEL_TOT) ? g_srtBox[kk] : make_float4(0.f, 0.f, 0.f, 0.f);
        kb[t] = b;
        ka[t] = fmaxf(b.z - b.x, 0.f) * fmaxf(b.w - b.y, 0.f);
    }
    __syncthreads();
    int j = jbase + tid;
    if (j >= SEL_TOT) return;
    float4 bj = g_srtBox[j];
    float aj = fmaxf(bj.z - bj.x, 0.f) * fmaxf(bj.w - bj.y, 0.f);
    int w0 = kbase >> 5;
    for (int wi = 0; wi < KSLAB / 32; wi++) {
        unsigned word = 0u;
        int tb = wi * 32;
        if (kbase + tb < j) {
            #pragma unroll
            for (int t = 0; t < 32; t++) {
                int k = kbase + tb + t;
                float4 bk = kb[tb + t];
                float iy1 = fmaxf(bk.x, bj.x), ix1 = fmaxf(bk.y, bj.y);
                float iy2 = fminf(bk.z, bj.z), ix2 = fminf(bk.w, bj.w);
                float inter = fmaxf(iy2 - iy1, 0.f) * fmaxf(ix2 - ix1, 0.f);
                float uni = aj + ka[tb + t] - inter;
                bool bit = (k < j) && (inter > 0.5f * fmaxf(uni, 1e-9f));
                if (bit) word |= (1u << t);
            }
        }
        g_Mt[(size_t)(w0 + wi) * SEL_PAD2 + j] = word;
    }
}

// -------- 5. all 16 Jacobi iterations, sparse masks (grid barrier) ---------
// hard-spin barrier: no nanosleep — detection latency ~1 L2 round trip
__device__ __forceinline__ void gridBarrier(unsigned nb) {
    __threadfence();
    __syncthreads();
    if (threadIdx.x == 0) {
        unsigned my = __ldcg(&g_barGen);
        if (atomicAdd(&g_barCount, 1u) == nb - 1u) {
            atomicExch(&g_barCount, 0u);
            __threadfence();
            atomicAdd(&g_barGen, 1u);
        } else {
            while (__ldcg(&g_barGen) == my) { }
        }
    }
    __syncthreads();
}

extern __shared__ unsigned sMdyn[];              // 128 * MPITCH words
__global__ void nmsKernel() {
    __shared__ unsigned sK[WW];
    __shared__ unsigned char sIdx[128][WW];      // nonzero-word indices (17 KB)
    int tid = threadIdx.x;
    int j = blockIdx.x * 128 + tid;
    int lane = tid & 31;
    int wj = j >> 5;
    int wtop = (j > 0 && j < SEL_TOT) ? (((j - 1) >> 5) + 1) : 0;
    unsigned* mrow = sMdyn + tid * MPITCH;
    for (int w = 0; w < WW; w++)                  // coalesced across tid
        mrow[w] = g_Mt[(size_t)w * SEL_PAD2 + j];
    // compact to nonzero (value, index) pairs — in place (write pos <= read pos)
    int nzc = 0;
    for (int w = 0; w < wtop; w++) {
        unsigned v = mrow[w];
        if (v) { mrow[nzc] = v; sIdx[tid][nzc] = (unsigned char)w; nzc++; }
    }
    unsigned lastBal = 0xFFFFFFFFu;

    for (int t = 0; t < 16; t++) {
        if (t == 0) {
            for (int w = tid; w < WW; w += 128) sK[w] = 0xFFFFFFFFu;
        } else {
            const unsigned* src = g_keep[(t - 1) & 1];
            for (int w = tid; w < WW; w += 128) sK[w] = __ldcg(&src[w]);
        }
        __syncthreads();
        unsigned acc = 0u;
        for (int i = 0; i < nzc; i++)
            acc |= mrow[i] & sK[sIdx[tid][i]];
        bool keepNew = (acc == 0u);
        unsigned bal = __ballot_sync(0xffffffffu, keepNew);
        unsigned oldw = sK[wj];
        if (lane == 0) {
            __stcg(&g_keep[t & 1][wj], bal);
            if (bal != oldw) atomicOr(&g_changeArr[t], 1u);
        }
        lastBal = bal;
        gridBarrier(JTILES);
        unsigned chg = __ldcg(&g_changeArr[t]);
        __syncthreads();
        if (chg == 0u) break;
    }
    if (lane == 0) __stcg(&g_keepOut[wj], lastBal);
}

// ------------- 6. final top-100 (block 0) + parallel state reset -----------
__global__ void finalKernel(float* __restrict__ out, const float* __restrict__ loc,
                            int out_size) {
    int tid = threadIdx.x;
    // all blocks: reset a slice of state for the next execution
    {
        int total = 5 * HBINS;
        int per = (total + gridDim.x - 1) / gridDim.x;
        int lo = blockIdx.x * per, hi = lo + per; if (hi > total) hi = total;
        for (int i = lo + tid; i < hi; i += blockDim.x) g_hist[i] = 0u;
    }
    if (blockIdx.x != 0) return;
    if (tid < 5) { g_cg[tid] = 0; g_cntTie[tid] = 0; }

    __shared__ unsigned kw[WW];
    __shared__ int wpfx[WW + 1];
    __shared__ int sel[100];
    __shared__ int sKtot;

    for (int w = tid; w < WW; w += blockDim.x) {
        unsigned vb = 0u;
        int base = w * 32;
        #pragma unroll 4
        for (int b = 0; b < 32; b++) {
            int j = base + b;
            if (j < SEL_TOT && g_srtValid[j]) vb |= (1u << b);
        }
        kw[w] = g_keepOut[w] & vb;
    }
    __syncthreads();
    if (tid == 0) {
        int acc = 0;
        for (int w = 0; w < WW; w++) { wpfx[w] = acc; acc += __popc(kw[w]); }
        wpfx[WW] = acc;
        sKtot = acc;
    }
    __syncthreads();
    int Ktot = sKtot;
    for (int j = tid; j < SEL_TOT; j += blockDim.x) {
        int w = j >> 5, b = j & 31;
        unsigned below = (b == 0) ? 0u : (kw[w] & (0xFFFFFFFFu >> (32 - b)));
        int kr = wpfx[w] + __popc(below);
        bool kp = (kw[w] >> b) & 1u;
        if (kp) {
            if (kr < 100) sel[kr] = j;
        } else if (Ktot < 100) {
            int pos = Ktot + (j - kr);
            if (pos < 100) sel[pos] = j;
        }
    }
    __syncthreads();
    if (tid < 100) {
        int j = sel[tid];
        int w = j >> 5, b = j & 31;
        bool kp = (kw[w] >> b) & 1u;
        float vy1 = loc[0], vx1 = loc[1], vy2 = loc[2], vx2 = loc[3];
        float oh = loc[4], ow = loc[5];
        float sy = oh / fmaxf(vy2 - vy1, 1e-6f);
        float sx = ow / fmaxf(vx2 - vx1, 1e-6f);
        float4 bx = g_srtBox[j];
        if (tid * 4 + 3 < out_size) {
            out[tid * 4 + 0] = (bx.x - vy1) * sy;
            out[tid * 4 + 1] = (bx.y - vx1) * sx;
            out[tid * 4 + 2] = (bx.z - vy1) * sy;
            out[tid * 4 + 3] = (bx.w - vx1) * sx;
        }
        if (400 + tid < out_size) out[400 + tid] = (float)g_srtCls[j];
        if (500 + tid < out_size) out[500 + tid] = kp ? g_srtScore[j] : 0.0f;
    }
}

// ---------------- host launcher --------------------------------------------
extern "C" void kernel_launch(void* const* d_in, const int* in_sizes, int n_in,
                              void* d_out, int out_size) {
    const float *cls[5] = {0, 0, 0, 0, 0};
    const float *reg[5] = {0, 0, 0, 0, 0};
    const float *loc = 0;
    for (int i = 0; i < n_in; i++) {
        switch (in_sizes[i]) {
            case 5242880: cls[0] = (const float*)d_in[i]; break;
            case 1310720: cls[1] = (const float*)d_in[i]; break;
            case 327680:  cls[2] = (const float*)d_in[i]; break;
            case 81920:   cls[3] = (const float*)d_in[i]; break;
            case 20480:   cls[4] = (const float*)d_in[i]; break;
            case 262144:  reg[0] = (const float*)d_in[i]; break;
            case 65536:   reg[1] = (const float*)d_in[i]; break;
            case 16384:   reg[2] = (const float*)d_in[i]; break;
            case 4096:    reg[3] = (const float*)d_in[i]; break;
            case 1024:    reg[4] = (const float*)d_in[i]; break;
            case 6:       loc    = (const float*)d_in[i]; break;
            default: break;
        }
    }
    static int smemSet = 0;
    if (!smemSet) {
        cudaFuncSetAttribute(nmsKernel, cudaFuncAttributeMaxDynamicSharedMemorySize,
                             128 * MPITCH * 4);
        smemSet = 1;
    }
    int blocks = (N_TOT * 32 + 255) / 256;
    scoreKernel<<<blocks, 256>>>(cls[0], cls[1], cls[2], cls[3], cls[4]);
    pivotKernel<<<5, 256>>>();
    fillKernel<<<341, 256>>>(reg[0], reg[1], reg[2], reg[3], reg[4], loc);
    dim3 rg(5, EQCAP / RTILE);
    refineKernel<<<rg, 256>>>(reg[0], reg[1], reg[2], reg[3], reg[4], loc);
    rankKernel<<<68, 512>>>();
    dim3 mg(JTILES, NSLAB);
    matrixKernel<<<mg, 128>>>();
    nmsKernel<<<JTILES, 128, 128 * MPITCH * 4>>>();
    finalKernel<<<17, 256>>>((float*)d_out, loc, out_size);
}